// round 15
// baseline (speedup 1.0000x reference)
#include <cuda_runtime.h>
#include <cuda_bf16.h>
#include <cuda_fp16.h>
#include <math.h>
#include <stdint.h>

// ---- model constants ----
#define Vv   32000
#define Dd   512
#define Ll   8
#define Hh   4
#define Dh   128
#define Ff   2048
#define Bb   2
#define Tt   1024
#define Nrows (Bb*Tt)          // 2048
#define ND   (Nrows*Dd)        // 1048576
#define NF   (Nrows*Ff)        // 4194304
#define DDm  (Dd*Dd)
#define CSZ  64                // wkv chunk length
#define NCH  (Tt/CSZ)          // 16 chunks

// ---- fp32 scratch ----
__device__ float g_h [ND];
__device__ float g_r [ND];
__device__ float g_k [ND];
__device__ float g_v [ND];
__device__ float g_w [ND];
__device__ float g_g [ND];
__device__ float g_y [ND];
__device__ float g_Sb[(size_t)Bb*Hh*NCH*Dh*Dh];
__device__ float g_wt[Bb*Hh*NCH*Dh];

// ---- bf16 hi/lo activation buffers ([M][K] row-major) ----
__device__ __nv_bfloat16 g_x5h[5*ND], g_x5l[5*ND];
__device__ __nv_bfloat16 g_ffh[NF],  g_ffl[NF];
__device__ __nv_bfloat16 g_hnh[ND],  g_hnl[ND];
__device__ __nv_bfloat16 g_gnh[ND],  g_gnl[ND];

// ---- fp16 buffers for the 1-pass logits GEMM ----
__device__ __half g_e16[(size_t)Vv*Dd];
__device__ __half g_h16[ND];

// ---- bf16 hi/lo transposed weight caches ([N][K] row-major) ----
__device__ __nv_bfloat16 g_pTh[(size_t)Ll*5*DDm], g_pTl[(size_t)Ll*5*DDm];
__device__ __nv_bfloat16 g_oTh[(size_t)Ll*DDm],   g_oTl[(size_t)Ll*DDm];
__device__ __nv_bfloat16 g_1Th[(size_t)Ll*Dd*Ff], g_1Tl[(size_t)Ll*Dd*Ff];
__device__ __nv_bfloat16 g_2Th[(size_t)Ll*Ff*Dd], g_2Tl[(size_t)Ll*Ff*Dd];

// =========================================================================
// PTX helpers (baseline sm_80+ — legal on compute_103)
// =========================================================================
__device__ __forceinline__ uint32_t s2u(const void* p) {
    uint32_t a;
    asm("{ .reg .u64 t; cvta.to.shared.u64 t, %1; cvt.u32.u64 %0, t; }"
        : "=r"(a) : "l"(p));
    return a;
}
__device__ __forceinline__ void cp16(uint32_t d, const void* s) {
    asm volatile("cp.async.cg.shared.global [%0], [%1], 16;" :: "r"(d), "l"(s));
}
__device__ __forceinline__ void ldm_x4(uint32_t* r, uint32_t addr) {
    asm volatile("ldmatrix.sync.aligned.m8n8.x4.shared.b16 {%0,%1,%2,%3}, [%4];"
        : "=r"(r[0]), "=r"(r[1]), "=r"(r[2]), "=r"(r[3]) : "r"(addr));
}
__device__ __forceinline__ void mma_bf16(float* d, const uint32_t* a, const uint32_t* b) {
    asm volatile(
        "mma.sync.aligned.m16n8k16.row.col.f32.bf16.bf16.f32 "
        "{%0,%1,%2,%3}, {%4,%5,%6,%7}, {%8,%9}, {%0,%1,%2,%3};"
        : "+f"(d[0]), "+f"(d[1]), "+f"(d[2]), "+f"(d[3])
        : "r"(a[0]), "r"(a[1]), "r"(a[2]), "r"(a[3]), "r"(b[0]), "r"(b[1]));
}
__device__ __forceinline__ void mma_f16(float* d, const uint32_t* a, const uint32_t* b) {
    asm volatile(
        "mma.sync.aligned.m16n8k16.row.col.f32.f16.f16.f32 "
        "{%0,%1,%2,%3}, {%4,%5,%6,%7}, {%8,%9}, {%0,%1,%2,%3};"
        : "+f"(d[0]), "+f"(d[1]), "+f"(d[2]), "+f"(d[3])
        : "r"(a[0]), "r"(a[1]), "r"(a[2]), "r"(a[3]), "r"(b[0]), "r"(b[1]));
}

#define SROWB  144          // padded row stride (64 elems * 2B = 128B + 16B pad)
#define MM_SMEM2 110592     // MF=2 3-pass: 2 stages * (2*64 + 2*128) rows * 144B
#define MM_SMEM1 73728      // MF=4 1-pass: 2 stages * (1*128 + 1*128) rows * 144B

// =========================================================================
// multi-pass mma GEMM. CTA tile (MF*32) x 128, K-step 64, 2 stages.
// NPASS=3: A hi/lo, B hi/lo (bf16). NPASS=1: A hi, B hi (fp16).
// epi: 0=store fp32, 1=add fp32, 2=gelu->hi/lo bf16, 3=wact, 4=silu
// =========================================================================
template<int MF, int NPASS, bool FP16>
__device__ __forceinline__ void mma_gemm_body(
    const void* __restrict__ Ahv, const void* __restrict__ Alv,
    const void* __restrict__ Bhv, const void* __restrict__ Blv,
    float* __restrict__ C, __nv_bfloat16* __restrict__ Ch, __nv_bfloat16* __restrict__ Cl,
    int N, int K, int epi, const float* __restrict__ aux)
{
    const __nv_bfloat16* Ah = (const __nv_bfloat16*)Ahv;
    const __nv_bfloat16* Al = (const __nv_bfloat16*)Alv;
    const __nv_bfloat16* Bh = (const __nv_bfloat16*)Bhv;
    const __nv_bfloat16* Bl = (const __nv_bfloat16*)Blv;

    extern __shared__ char sm[];
    uint32_t sb = s2u(sm);
    const int BM  = MF * 32;
    const int NA  = (NPASS >= 2) ? 2 : 1;
    const int NB  = (NPASS == 3) ? 2 : 1;
    const int AB  = BM * SROWB;
    const int BB  = 128 * SROWB;
    const int STG = NA * AB + NB * BB;
    const int AH_OFF = 0, AL_OFF = AB, BH_OFF = NA * AB, BL_OFF = NA * AB + BB;

    int tid = threadIdx.x, lane = tid & 31, wid = tid >> 5;
    int m0 = blockIdx.y * BM, n0 = blockIdx.x * 128;
    int m0w = (wid & 1) * (MF * 16), n0w = (wid >> 1) * 32;

    float acc[MF][4][4];
    #pragma unroll
    for (int a = 0; a < MF; a++)
        #pragma unroll
        for (int b = 0; b < 4; b++)
            #pragma unroll
            for (int c = 0; c < 4; c++) acc[a][b][c] = 0.0f;

    const int nt = K >> 6;
    int arow = tid >> 3, ac = (tid & 7) * 8;
    uint32_t aso = arow * SROWB + (tid & 7) * 16;

    // prologue: stage 0
    {
        uint32_t base = sb;
        #pragma unroll
        for (int i = 0; i < MF; i++) {
            int row = arow + i * 32;
            uint32_t so = aso + i * 32 * SROWB;
            size_t ga = (size_t)(m0 + row) * K + ac;
            cp16(base + AH_OFF + so, Ah + ga);
            if (NPASS >= 2) cp16(base + AL_OFF + so, Al + ga);
        }
        #pragma unroll
        for (int i = 0; i < 4; i++) {
            int row = arow + i * 32;
            uint32_t so = aso + i * 32 * SROWB;
            size_t gb = (size_t)(n0 + row) * K + ac;
            cp16(base + BH_OFF + so, Bh + gb);
            if (NPASS == 3) cp16(base + BL_OFF + so, Bl + gb);
        }
        asm volatile("cp.async.commit_group;" ::: "memory");
    }

    for (int t = 0; t < nt; t++) {
        if (t + 1 < nt) {
            int k0 = (t + 1) << 6;
            uint32_t base = sb + ((t + 1) & 1) * STG;
            #pragma unroll
            for (int i = 0; i < MF; i++) {
                int row = arow + i * 32;
                uint32_t so = aso + i * 32 * SROWB;
                size_t ga = (size_t)(m0 + row) * K + k0 + ac;
                cp16(base + AH_OFF + so, Ah + ga);
                if (NPASS >= 2) cp16(base + AL_OFF + so, Al + ga);
            }
            #pragma unroll
            for (int i = 0; i < 4; i++) {
                int row = arow + i * 32;
                uint32_t so = aso + i * 32 * SROWB;
                size_t gb = (size_t)(n0 + row) * K + k0 + ac;
                cp16(base + BH_OFF + so, Bh + gb);
                if (NPASS == 3) cp16(base + BL_OFF + so, Bl + gb);
            }
            asm volatile("cp.async.commit_group;" ::: "memory");
            asm volatile("cp.async.wait_group 1;" ::: "memory");
        } else {
            asm volatile("cp.async.wait_group 0;" ::: "memory");
        }
        __syncthreads();

        uint32_t base = sb + (t & 1) * STG;
        #pragma unroll
        for (int kk = 0; kk < 4; kk++) {
            uint32_t aoff = (uint32_t)((m0w + (lane & 15)) * SROWB
                           + kk * 32 + (lane >> 4) * 16);
            uint32_t boff = (uint32_t)((n0w + (lane & 7) + ((lane >> 4) << 3)) * SROWB
                           + kk * 32 + ((lane >> 3) & 1) * 16);
            uint32_t aH[MF][4], aL[MF][4], bH[2][4], bL[2][4];
            #pragma unroll
            for (int mf = 0; mf < MF; mf++)
                ldm_x4(aH[mf], base + AH_OFF + aoff + mf * 16 * SROWB);
            #pragma unroll
            for (int bb = 0; bb < 2; bb++)
                ldm_x4(bH[bb], base + BH_OFF + boff + bb * 16 * SROWB);
            #pragma unroll
            for (int mf = 0; mf < MF; mf++)
                #pragma unroll
                for (int nf = 0; nf < 4; nf++) {
                    if (FP16) mma_f16 (acc[mf][nf], aH[mf], &bH[nf >> 1][(nf & 1) * 2]);
                    else      mma_bf16(acc[mf][nf], aH[mf], &bH[nf >> 1][(nf & 1) * 2]);
                }
            if (NPASS >= 2) {
                #pragma unroll
                for (int mf = 0; mf < MF; mf++)
                    ldm_x4(aL[mf], base + AL_OFF + aoff + mf * 16 * SROWB);
                #pragma unroll
                for (int mf = 0; mf < MF; mf++)
                    #pragma unroll
                    for (int nf = 0; nf < 4; nf++) {
                        if (FP16) mma_f16 (acc[mf][nf], aL[mf], &bH[nf >> 1][(nf & 1) * 2]);
                        else      mma_bf16(acc[mf][nf], aL[mf], &bH[nf >> 1][(nf & 1) * 2]);
                    }
            }
            if (NPASS == 3) {
                #pragma unroll
                for (int bb = 0; bb < 2; bb++)
                    ldm_x4(bL[bb], base + BL_OFF + boff + bb * 16 * SROWB);
                #pragma unroll
                for (int mf = 0; mf < MF; mf++)
                    #pragma unroll
                    for (int nf = 0; nf < 4; nf++) {
                        if (FP16) mma_f16 (acc[mf][nf], aH[mf], &bL[nf >> 1][(nf & 1) * 2]);
                        else      mma_bf16(acc[mf][nf], aH[mf], &bL[nf >> 1][(nf & 1) * 2]);
                    }
            }
        }
        __syncthreads();
    }

    // ---- epilogue ----
    int qr = lane >> 2, qc = (lane & 3) * 2;
    #pragma unroll
    for (int mf = 0; mf < MF; mf++) {
        #pragma unroll
        for (int nf = 0; nf < 4; nf++) {
            #pragma unroll
            for (int half = 0; half < 2; half++) {
                int row = m0 + m0w + mf * 16 + qr + half * 8;
                int col = n0 + n0w + nf * 8 + qc;
                float x = acc[mf][nf][half * 2 + 0];
                float y = acc[mf][nf][half * 2 + 1];
                size_t o = (size_t)row * N + col;
                if (epi == 0) {
                    *(float2*)(C + o) = make_float2(x, y);
                } else if (epi == 1) {
                    float2 old = *(const float2*)(C + o);
                    *(float2*)(C + o) = make_float2(old.x + x, old.y + y);
                } else if (epi == 2) {
                    x = 0.5f * x * (1.0f + erff(x * 0.70710678118654752f));
                    y = 0.5f * y * (1.0f + erff(y * 0.70710678118654752f));
                    __nv_bfloat162 hv = __floats2bfloat162_rn(x, y);
                    float lx = x - __bfloat162float(__low2bfloat16(hv));
                    float ly = y - __bfloat162float(__high2bfloat16(hv));
                    *(__nv_bfloat162*)(Ch + o) = hv;
                    *(__nv_bfloat162*)(Cl + o) = __floats2bfloat162_rn(lx, ly);
                } else if (epi == 3) {
                    x = expf(-expf(x + aux[col]));
                    y = expf(-expf(y + aux[col + 1]));
                    *(float2*)(C + o) = make_float2(x, y);
                } else {
                    x = x / (1.0f + expf(-x));
                    y = y / (1.0f + expf(-y));
                    *(float2*)(C + o) = make_float2(x, y);
                }
            }
        }
    }
}

__global__ void __launch_bounds__(256, 2)
mma_gemm2(const __nv_bfloat16* __restrict__ Ah, const __nv_bfloat16* __restrict__ Al,
          const __nv_bfloat16* __restrict__ Bh, const __nv_bfloat16* __restrict__ Bl,
          float* __restrict__ C, __nv_bfloat16* __restrict__ Ch,
          __nv_bfloat16* __restrict__ Cl, int N, int K, int epi,
          const float* __restrict__ aux) {
    mma_gemm_body<2, 3, false>(Ah, Al, Bh, Bl, C, Ch, Cl, N, K, epi, aux);
}

// fp16 1-pass GEMM (logits)
__global__ void __launch_bounds__(256, 2)
mma_gemm_h1(const __half* __restrict__ Ah, const __half* __restrict__ Bh,
            float* __restrict__ C, int N, int K) {
    mma_gemm_body<4, 1, true>(Ah, nullptr, Bh, nullptr, C, nullptr, nullptr, N, K, 0, nullptr);
}

// batched 5-projection
__global__ void __launch_bounds__(256, 2)
proj_mma(const __nv_bfloat16* __restrict__ x5h, const __nv_bfloat16* __restrict__ x5l,
         const __nv_bfloat16* __restrict__ Ph, const __nv_bfloat16* __restrict__ Pl,
         int l, const float* __restrict__ w0,
         float* __restrict__ Cr, float* __restrict__ Ck, float* __restrict__ Cv,
         float* __restrict__ Cw, float* __restrict__ Cg) {
    int z = blockIdx.z;
    size_t wo = ((size_t)l * 5 + z) * DDm;
    float* C = (z == 0) ? Cr : (z == 1) ? Ck : (z == 2) ? Cv : (z == 3) ? Cw : Cg;
    int epi = (z == 3) ? 3 : (z == 4) ? 4 : 0;
    mma_gemm_body<2, 3, false>(x5h + (size_t)z * ND, x5l + (size_t)z * ND,
                               Ph + wo, Pl + wo, C, nullptr, nullptr, Dd, Dd, epi, w0);
}

// =========================================================================
// weight prep: transpose [K,N] -> [N,K] with bf16 hi/lo split
// =========================================================================
__global__ void tsplit(const float* __restrict__ W, __nv_bfloat16* __restrict__ oh,
                       __nv_bfloat16* __restrict__ ol, int K, int N) {
    __shared__ float ts[32][33];
    size_t mo = (size_t)blockIdx.z * K * N;
    int n0 = blockIdx.x * 32, k0 = blockIdx.y * 32;
    int tx = threadIdx.x, ty = threadIdx.y;
    #pragma unroll
    for (int r = 0; r < 4; r++)
        ts[ty + 8 * r][tx] = W[mo + (size_t)(k0 + ty + 8 * r) * N + n0 + tx];
    __syncthreads();
    #pragma unroll
    for (int r = 0; r < 4; r++) {
        float a = ts[tx][ty + 8 * r];
        float h = __bfloat162float(__float2bfloat16(a));
        size_t o = mo + (size_t)(n0 + ty + 8 * r) * K + k0 + tx;
        oh[o] = __float2bfloat16(a);
        ol[o] = __float2bfloat16(a - h);
    }
}

// proj (z<40) + Wo (z in [40,48))
__global__ void tsplit_projWo(const float* __restrict__ Wr, const float* __restrict__ Wk,
                              const float* __restrict__ Wv, const float* __restrict__ Ww,
                              const float* __restrict__ Wg, const float* __restrict__ Wo,
                              __nv_bfloat16* __restrict__ ph, __nv_bfloat16* __restrict__ pl,
                              __nv_bfloat16* __restrict__ ohd, __nv_bfloat16* __restrict__ old_) {
    __shared__ float ts[32][33];
    int z = blockIdx.z;
    const float* W;
    __nv_bfloat16 *oh, *ol;
    size_t mo;
    if (z < 40) {
        int p = z % 5, l = z / 5;
        W = ((p == 0) ? Wr : (p == 1) ? Wk : (p == 2) ? Wv :
             (p == 3) ? Ww : Wg) + (size_t)l * DDm;
        mo = (size_t)z * DDm;
        oh = ph; ol = pl;
    } else {
        int l = z - 40;
        W = Wo + (size_t)l * DDm;
        mo = (size_t)l * DDm;
        oh = ohd; ol = old_;
    }
    int n0 = blockIdx.x * 32, k0 = blockIdx.y * 32;
    int tx = threadIdx.x, ty = threadIdx.y;
    #pragma unroll
    for (int r = 0; r < 4; r++)
        ts[ty + 8 * r][tx] = W[(size_t)(k0 + ty + 8 * r) * Dd + n0 + tx];
    __syncthreads();
    #pragma unroll
    for (int r = 0; r < 4; r++) {
        float a = ts[tx][ty + 8 * r];
        float h = __bfloat162float(__float2bfloat16(a));
        size_t o = mo + (size_t)(n0 + ty + 8 * r) * Dd + k0 + tx;
        oh[o] = __float2bfloat16(a);
        ol[o] = __float2bfloat16(a - h);
    }
}

__global__ void esplit_f16(const float* __restrict__ e, __half* __restrict__ e16) {
    int idx = blockIdx.x * blockDim.x + threadIdx.x;
    e16[idx] = __float2half(e[idx]);
}

// =========================================================================
// embedding gather
// =========================================================================
__global__ void embed_kernel(const int* __restrict__ tok,
                             const float* __restrict__ emb,
                             float* __restrict__ h) {
    int idx = blockIdx.x * blockDim.x + threadIdx.x;
    int row = idx >> 7;
    int c4  = idx & 127;
    ((float4*)h)[idx] = ((const float4*)emb)[(size_t)tok[row] * 128 + c4];
}

// =========================================================================
// fused rmsnorm + token-shift + 5-way lerp -> hi/lo bf16
// =========================================================================
__global__ void __launch_bounds__(128)
rms_mix5(const float* __restrict__ h, const float* __restrict__ lnw,
         const float* __restrict__ mix,
         __nv_bfloat16* __restrict__ xh, __nv_bfloat16* __restrict__ xl) {
    int row = blockIdx.x, tid = threadIdx.x;
    int t = row & (Tt - 1);
    float4 a = ((const float4*)(h + (size_t)row * Dd))[tid];
    float4 p = (t == 0) ? make_float4(0, 0, 0, 0)
                        : ((const float4*)(h + (size_t)(row - 1) * Dd))[tid];
    float sc_ = a.x*a.x + a.y*a.y + a.z*a.z + a.w*a.w;
    float sp_ = p.x*p.x + p.y*p.y + p.z*p.z + p.w*p.w;
    #pragma unroll
    for (int s = 16; s > 0; s >>= 1) {
        sc_ += __shfl_xor_sync(0xffffffffu, sc_, s);
        sp_ += __shfl_xor_sync(0xffffffffu, sp_, s);
    }
    __shared__ float rc[4], rp[4];
    if ((tid & 31) == 0) { rc[tid >> 5] = sc_; rp[tid >> 5] = sp_; }
    __syncthreads();
    float totc = rc[0] + rc[1] + rc[2] + rc[3];
    float totp = rp[0] + rp[1] + rp[2] + rp[3];
    float scc = rsqrtf(totc * (1.0f / Dd) + 1e-6f);
    float scp = (t == 0) ? 0.0f : rsqrtf(totp * (1.0f / Dd) + 1e-6f);
    float4 wv = ((const float4*)lnw)[tid];
    float cn[4] = {a.x * scc * wv.x, a.y * scc * wv.y, a.z * scc * wv.z, a.w * scc * wv.w};
    float pn[4] = {p.x * scp * wv.x, p.y * scp * wv.y, p.z * scp * wv.z, p.w * scp * wv.w};
    int c0 = tid * 4;
    size_t ro = (size_t)row * Dd + c0;
    #pragma unroll
    for (int j = 0; j < 5; j++) {
        #pragma unroll
        for (int i = 0; i < 4; i++) {
            float v = fmaf(pn[i] - cn[i], mix[j * Dd + c0 + i], cn[i]);
            float hv = __bfloat162float(__float2bfloat16(v));
            xh[(size_t)j * ND + ro + i] = __float2bfloat16(v);
            xl[(size_t)j * ND + ro + i] = __float2bfloat16(v - hv);
        }
    }
}

// hi/lo-out rmsnorm -> bf16 (feeds FFN W1)
__global__ void rmsnorm_split_kernel(const float* __restrict__ x,
                                     const float* __restrict__ w,
                                     __nv_bfloat16* __restrict__ oh,
                                     __nv_bfloat16* __restrict__ ol) {
    int row = blockIdx.x;
    int tid = threadIdx.x;
    float4 a = ((const float4*)(x + (size_t)row * Dd))[tid];
    float ss = a.x*a.x + a.y*a.y + a.z*a.z + a.w*a.w;
    #pragma unroll
    for (int s = 16; s > 0; s >>= 1) ss += __shfl_xor_sync(0xffffffffu, ss, s);
    __shared__ float sred[4];
    if ((tid & 31) == 0) sred[tid >> 5] = ss;
    __syncthreads();
    float tot = sred[0] + sred[1] + sred[2] + sred[3];
    float sc  = rsqrtf(tot * (1.0f / Dd) + 1e-6f);
    float4 wv = ((const float4*)w)[tid];
    float vv[4] = {a.x * sc * wv.x, a.y * sc * wv.y, a.z * sc * wv.z, a.w * sc * wv.w};
    size_t o = (size_t)row * Dd + tid * 4;
    #pragma unroll
    for (int i = 0; i < 4; i++) {
        float h = __bfloat162float(__float2bfloat16(vv[i]));
        oh[o + i] = __float2bfloat16(vv[i]);
        ol[o + i] = __float2bfloat16(vv[i] - h);
    }
}

// fp16-out rmsnorm (feeds 1-pass logits GEMM)
__global__ void rmsnorm_f16(const float* __restrict__ x,
                            const float* __restrict__ w,
                            __half* __restrict__ oh) {
    int row = blockIdx.x;
    int tid = threadIdx.x;
    float4 a = ((const float4*)(x + (size_t)row * Dd))[tid];
    float ss = a.x*a.x + a.y*a.y + a.z*a.z + a.w*a.w;
    #pragma unroll
    for (int s = 16; s > 0; s >>= 1) ss += __shfl_xor_sync(0xffffffffu, ss, s);
    __shared__ float sred[4];
    if ((tid & 31) == 0) sred[tid >> 5] = ss;
    __syncthreads();
    float tot = sred[0] + sred[1] + sred[2] + sred[3];
    float sc  = rsqrtf(tot * (1.0f / Dd) + 1e-6f);
    float4 wv = ((const float4*)w)[tid];
    size_t o = (size_t)row * Dd + tid * 4;
    oh[o + 0] = __float2half(a.x * sc * wv.x);
    oh[o + 1] = __float2half(a.y * sc * wv.y);
    oh[o + 2] = __float2half(a.z * sc * wv.z);
    oh[o + 3] = __float2half(a.w * sc * wv.w);
}

// =========================================================================
// WKV phase 1: per-chunk local recurrence, single-sync pipelined.
// =========================================================================
__global__ void __launch_bounds__(128, 3)
wkv_chunk_kernel(float* __restrict__ r, const float* __restrict__ k,
                 const float* __restrict__ v, const float* __restrict__ w,
                 const float* __restrict__ u, float* __restrict__ y,
                 float* __restrict__ Sb, float* __restrict__ wt) {
    int blk = blockIdx.x;
    int bh  = blk / NCH;
    int ch  = blk % NCH;
    int b = bh >> 2, h = bh & 3;
    int j = threadIdx.x;
    int lane = j & 31, warp = j >> 5;
    __shared__ float4 s[2][Dh];
    __shared__ float red[2][4];
    float uj = u[h * Dh + j];
    float S[Dh];
    #pragma unroll
    for (int i = 0; i < Dh; i++) S[i] = 0.0f;
    float p = 1.0f;
    size_t off = (size_t)b * Tt * Dd + (size_t)(ch * CSZ) * Dd + h * Dh + j;

    // preload step 0 into buffer 0
    {
        float rv = r[off], kv_ = k[off], wv = w[off], vv0 = v[off];
        s[0][j] = make_float4(rv, kv_, wv, vv0);
        float prod = rv * uj * kv_;
        #pragma unroll
        for (int sh = 16; sh > 0; sh >>= 1)
            prod += __shfl_xor_sync(0xffffffffu, prod, sh);
        if (lane == 0) red[0][warp] = prod;
        r[off] = rv * p;
        p *= wv;
    }

    for (int t = 0; t < CSZ; t++, off += Dd) {
        int buf = t & 1;
        __syncthreads();
        float vv = s[buf][j].w;
        float ruk = red[buf][0] + red[buf][1] + red[buf][2] + red[buf][3];
        if (t + 1 < CSZ) {
            size_t off2 = off + Dd;
            float rv = r[off2], kv_ = k[off2], wv = w[off2], vv2 = v[off2];
            s[buf ^ 1][j] = make_float4(rv, kv_, wv, vv2);
            float prod = rv * uj * kv_;
            #pragma unroll
            for (int sh = 16; sh > 0; sh >>= 1)
                prod += __shfl_xor_sync(0xffffffffu, prod, sh);
            if (lane == 0) red[buf ^ 1][warp] = prod;
            r[off2] = rv * p;
            p *= wv;
        }
        float acc = 0.0f;
        #pragma unroll
        for (int i = 0; i < Dh; i++) {
            float4 q = s[buf][i];
            acc = fmaf(q.x, S[i], acc);
            S[i] = fmaf(q.z, S[i], q.y * vv);
        }
        y[off] = fmaf(ruk, vv, acc);
    }
    wt[blk * Dh + j] = p;
    size_t base = (size_t)blk * Dh * Dh;
    #pragma unroll
    for (int i = 0; i < Dh; i++) Sb[base + (size_t)i * Dh + j] = S[i];
}

// =========================================================================
// WKV phase 2: parallel elementwise scan over chunks
// =========================================================================
__global__ void __launch_bounds__(256)
wkv_combine_kernel(float* __restrict__ Sb, const float* __restrict__ wt) {
    int idx = blockIdx.x * blockDim.x + threadIdx.x;
    int bh  = idx >> 14;
    int rem = idx & 16383;
    int i   = rem >> 7;
    float run = 0.0f;
    #pragma unroll 4
    for (int ch = 0; ch < NCH; ch++) {
        int blk = bh * NCH + ch;
        size_t o = ((size_t)blk << 14) + rem;
        float m = Sb[o];
        Sb[o] = run;
        run = fmaf(run, wt[blk * Dh + i], m);
    }
}

// =========================================================================
// WKV phase 3 + GroupNorm + gate, single-sync pipelined
// =========================================================================
__global__ void __launch_bounds__(128, 3)
wkv_inter_gn_kernel(const float* __restrict__ rt, const float* __restrict__ Sb,
                    const float* __restrict__ y, const float* __restrict__ g,
                    const float* __restrict__ gw, const float* __restrict__ gb,
                    __nv_bfloat16* __restrict__ oh, __nv_bfloat16* __restrict__ ol) {
    int blk = blockIdx.x;
    int bh  = blk / NCH;
    int ch  = blk % NCH;
    int b = bh >> 2, h = bh & 3;
    int j = threadIdx.x;
    int lane = j & 31, wid = j >> 5;
    float Scol[Dh];
    size_t base = (size_t)blk * Dh * Dh;
    #pragma unroll
    for (int i = 0; i < Dh; i++) Scol[i] = Sb[base + (size_t)i * Dh + j];
    __shared__ float sr[2][Dh];
    __shared__ float r1[2][4], r2[2][4];
    int c = h * Dh + j;
    float gwj = gw[c], gbj = gb[c];
    size_t off0 = (size_t)b * Tt * Dd + (size_t)(ch * CSZ) * Dd + h * Dh + j;

    sr[0][j] = rt[off0];

    float accP = 0.0f;
    size_t offP = 0;
    size_t off = off0;
    for (int t = 0; t <= CSZ; t++) {
        __syncthreads();
        if (t > 0) {
            int pb = (t - 1) & 1;
            float s1 = r1[pb][0] + r1[pb][1] + r1[pb][2] + r1[pb][3];
            float s2 = r2[pb][0] + r2[pb][1] + r2[pb][2] + r2[pb][3];
            float mu  = s1 * (1.0f / Dh);
            float var = s2 * (1.0f / Dh) - mu * mu;
            float nrm = (accP - mu) * rsqrtf(var + 1e-5f);
            float val = fmaf(nrm, gwj, gbj) * g[offP];
            float hv = __bfloat162float(__float2bfloat16(val));
            oh[offP] = __float2bfloat16(val);
            ol[offP] = __float2bfloat16(val - hv);
        }
        if (t < CSZ) {
            int buf = t & 1;
            float acc = y[off];
            #pragma unroll
            for (int i = 0; i < Dh; i++) acc = fmaf(sr[buf][i], Scol[i], acc);
            float s1 = acc, s2 = acc * acc;
            #pragma unroll
            for (int s = 16; s > 0; s >>= 1) {
                s1 += __shfl_xor_sync(0xffffffffu, s1, s);
                s2 += __shfl_xor_sync(0xffffffffu, s2, s);
            }
            if (lane == 0) { r1[buf][wid] = s1; r2[buf][wid] = s2; }
            if (t + 1 < CSZ) sr[buf ^ 1][j] = rt[off + Dd];
            accP = acc;
            offP = off;
            off += Dd;
        }
    }
}

// =========================================================================
// host driver
// =========================================================================
extern "C" void kernel_launch(void* const* d_in, const int* in_sizes, int n_in,
                              void* d_out, int out_size) {
    const int*   tokens = (const int*)  d_in[0];
    const float* embed  = (const float*)d_in[1];
    const float* ln1    = (const float*)d_in[2];
    const float* ln2    = (const float*)d_in[3];
    const float* lno    = (const float*)d_in[4];
    const float* mix    = (const float*)d_in[5];
    const float* Wr     = (const float*)d_in[6];
    const float* Wk     = (const float*)d_in[7];
    const float* Wv     = (const float*)d_in[8];
    const float* Wg     = (const float*)d_in[9];
    const float* Ww     = (const float*)d_in[10];
    const float* w0     = (const float*)d_in[11];
    const float* Wo     = (const float*)d_in[12];
    const float* u      = (const float*)d_in[13];
    const float* gnw    = (const float*)d_in[14];
    const float* gnb    = (const float*)d_in[15];
    const float* W1     = (const float*)d_in[16];
    const float* W2     = (const float*)d_in[17];
    float* out = (float*)d_out;

    float *h, *r, *k, *v, *w, *g, *y, *Sb, *wt;
    cudaGetSymbolAddress((void**)&h,  g_h);
    cudaGetSymbolAddress((void**)&r,  g_r);
    cudaGetSymbolAddress((void**)&k,  g_k);
    cudaGetSymbolAddress((void**)&v,  g_v);
    cudaGetSymbolAddress((void**)&w,  g_w);
    cudaGetSymbolAddress((void**)&g,  g_g);
    cudaGetSymbolAddress((void**)&y,  g_y);
    cudaGetSymbolAddress((void**)&Sb, g_Sb);
    cudaGetSymbolAddress((void**)&wt, g_wt);

    __nv_bfloat16 *x5h, *x5l, *ffh, *ffl, *hnh, *hnl, *gnh, *gnl;
    __nv_bfloat16 *pTh, *pTl, *oTh, *oTl, *t1h, *t1l, *t2h, *t2l;
    __half *e16, *h16;
    cudaGetSymbolAddress((void**)&x5h, g_x5h);
    cudaGetSymbolAddress((void**)&x5l, g_x5l);
    cudaGetSymbolAddress((void**)&ffh, g_ffh);
    cudaGetSymbolAddress((void**)&ffl, g_ffl);
    cudaGetSymbolAddress((void**)&hnh, g_hnh);
    cudaGetSymbolAddress((void**)&hnl, g_hnl);
    cudaGetSymbolAddress((void**)&gnh, g_gnh);
    cudaGetSymbolAddress((void**)&gnl, g_gnl);
    cudaGetSymbolAddress((void**)&pTh, g_pTh);
    cudaGetSymbolAddress((void**)&pTl, g_pTl);
    cudaGetSymbolAddress((void**)&oTh, g_oTh);
    cudaGetSymbolAddress((void**)&oTl, g_oTl);
    cudaGetSymbolAddress((void**)&t1h, g_1Th);
    cudaGetSymbolAddress((void**)&t1l, g_1Tl);
    cudaGetSymbolAddress((void**)&t2h, g_2Th);
    cudaGetSymbolAddress((void**)&t2l, g_2Tl);
    cudaGetSymbolAddress((void**)&e16, g_e16);
    cudaGetSymbolAddress((void**)&h16, g_h16);

    cudaFuncSetAttribute(mma_gemm2,   cudaFuncAttributeMaxDynamicSharedMemorySize, MM_SMEM2);
    cudaFuncSetAttribute(mma_gemm_h1, cudaFuncAttributeMaxDynamicSharedMemorySize, MM_SMEM1);
    cudaFuncSetAttribute(proj_mma,    cudaFuncAttributeMaxDynamicSharedMemorySize, MM_SMEM2);

    dim3 tb(32, 8);
    dim3 gridProj(4, 32, 5);          // 64x128 tiles, 5 projections
    dim3 grid512n(4, 32);             // 64x128 tiles for N=512 GEMMs
    dim3 gridF   (16, 32);            // W1 (N=2048)
    dim3 gridV   (250, 16);           // logits, 128x128 tiles (fp16 1-pass)

    // launch order: harness prepends 2 launches; ncu -s 5 -c 1 captures
    // global #6 = our #4 = proj_mma(l=0).
    tsplit_projWo<<<dim3(16, 16, 48), tb>>>(Wr, Wk, Wv, Ww, Wg, Wo, pTh, pTl, oTh, oTl);
    embed_kernel<<<(ND / 4) / 256, 256>>>(tokens, embed, h);
    rms_mix5<<<Nrows, 128>>>(h, ln1, mix, x5h, x5l);
    proj_mma<<<gridProj, 256, MM_SMEM2>>>(x5h, x5l, pTh, pTl, 0, w0, r, k, v, w, g);

    tsplit<<<dim3(Ff / 32, 16, Ll), tb>>>(W1, t1h, t1l, Dd, Ff);
    tsplit<<<dim3(16, Ff / 32, Ll), tb>>>(W2, t2h, t2l, Ff, Dd);
    esplit_f16<<<(Vv * Dd) / 256, 256>>>(embed, e16);

    for (int l = 0; l < Ll; l++) {
        if (l > 0) {
            rms_mix5<<<Nrows, 128>>>(h, ln1 + l * Dd, mix + (size_t)l * 5 * Dd, x5h, x5l);
            proj_mma<<<gridProj, 256, MM_SMEM2>>>(x5h, x5l, pTh, pTl, l, w0 + l * Dd,
                                                  r, k, v, w, g);
        }

        wkv_chunk_kernel  <<<Bb * Hh * NCH, 128>>>(r, k, v, w, u + l * Hh * Dh, y, Sb, wt);
        wkv_combine_kernel<<<(Bb * Hh * Dh * Dh) / 256, 256>>>(Sb, wt);
        wkv_inter_gn_kernel<<<Bb * Hh * NCH, 128>>>(r, Sb, y, g,
                                                    gnw + l * Dd, gnb + l * Dd, gnh, gnl);

        mma_gemm2<<<grid512n, 256, MM_SMEM2>>>(gnh, gnl, oTh + (size_t)l * DDm,
                                               oTl + (size_t)l * DDm, h, nullptr, nullptr,
                                               Dd, Dd, 1, nullptr);

        rmsnorm_split_kernel<<<Nrows, 128>>>(h, ln2 + l * Dd, hnh, hnl);
        mma_gemm2<<<gridF, 256, MM_SMEM2>>>(hnh, hnl, t1h + (size_t)l * Dd * Ff,
                                            t1l + (size_t)l * Dd * Ff, nullptr, ffh, ffl,
                                            Ff, Dd, 2, nullptr);
        mma_gemm2<<<grid512n, 256, MM_SMEM2>>>(ffh, ffl, t2h + (size_t)l * Ff * Dd,
                                               t2l + (size_t)l * Ff * Dd, h, nullptr, nullptr,
                                               Dd, Ff, 1, nullptr);
    }

    rmsnorm_f16<<<Nrows, 128>>>(h, lno, h16);
    mma_gemm_h1<<<gridV, 256, MM_SMEM1>>>(h16, e16, out, Vv, Dd);
}

// round 16
// speedup vs baseline: 1.1046x; 1.1046x over previous
#include <cuda_runtime.h>
#include <cuda_bf16.h>
#include <cuda_fp16.h>
#include <math.h>
#include <stdint.h>

// ---- model constants ----
#define Vv   32000
#define Dd   512
#define Ll   8
#define Hh   4
#define Dh   128
#define Ff   2048
#define Bb   2
#define Tt   1024
#define Nrows (Bb*Tt)          // 2048
#define ND   (Nrows*Dd)        // 1048576
#define NF   (Nrows*Ff)        // 4194304
#define DDm  (Dd*Dd)
#define CSZ  32                // wkv chunk length
#define NCH  (Tt/CSZ)          // 32 chunks

// ---- fp32 scratch ----
__device__ float g_h [ND];
__device__ float g_r [ND];
__device__ float g_k [ND];
__device__ float g_v [ND];
__device__ float g_w [ND];
__device__ float g_g [ND];
__device__ float g_y [ND];
__device__ float g_Sb[(size_t)Bb*Hh*NCH*Dh*Dh];
__device__ float g_wt[Bb*Hh*NCH*Dh];

// ---- bf16 hi/lo activation buffers ([M][K] row-major) ----
__device__ __nv_bfloat16 g_x5h[5*ND], g_x5l[5*ND];
__device__ __nv_bfloat16 g_ffh[NF],  g_ffl[NF];
__device__ __nv_bfloat16 g_hnh[ND],  g_hnl[ND];
__device__ __nv_bfloat16 g_gnh[ND],  g_gnl[ND];

// ---- fp16 buffers for the 1-pass logits GEMM ----
__device__ __half g_e16[(size_t)Vv*Dd];          // embed (fp16)
__device__ __half g_h16[ND];                     // final rmsnorm (fp16)

// ---- bf16 hi/lo transposed weight caches ([N][K] row-major) ----
__device__ __nv_bfloat16 g_pTh[(size_t)Ll*5*DDm], g_pTl[(size_t)Ll*5*DDm];
__device__ __nv_bfloat16 g_oTh[(size_t)Ll*DDm],   g_oTl[(size_t)Ll*DDm];
__device__ __nv_bfloat16 g_1Th[(size_t)Ll*Dd*Ff], g_1Tl[(size_t)Ll*Dd*Ff];
__device__ __nv_bfloat16 g_2Th[(size_t)Ll*Ff*Dd], g_2Tl[(size_t)Ll*Ff*Dd];

// =========================================================================
// PTX helpers (baseline sm_80+ — legal on compute_103)
// =========================================================================
__device__ __forceinline__ uint32_t s2u(const void* p) {
    uint32_t a;
    asm("{ .reg .u64 t; cvta.to.shared.u64 t, %1; cvt.u32.u64 %0, t; }"
        : "=r"(a) : "l"(p));
    return a;
}
__device__ __forceinline__ void cp16(uint32_t d, const void* s) {
    asm volatile("cp.async.cg.shared.global [%0], [%1], 16;" :: "r"(d), "l"(s));
}
__device__ __forceinline__ void ldm_x4(uint32_t* r, uint32_t addr) {
    asm volatile("ldmatrix.sync.aligned.m8n8.x4.shared.b16 {%0,%1,%2,%3}, [%4];"
        : "=r"(r[0]), "=r"(r[1]), "=r"(r[2]), "=r"(r[3]) : "r"(addr));
}
__device__ __forceinline__ void mma_bf16(float* d, const uint32_t* a, const uint32_t* b) {
    asm volatile(
        "mma.sync.aligned.m16n8k16.row.col.f32.bf16.bf16.f32 "
        "{%0,%1,%2,%3}, {%4,%5,%6,%7}, {%8,%9}, {%0,%1,%2,%3};"
        : "+f"(d[0]), "+f"(d[1]), "+f"(d[2]), "+f"(d[3])
        : "r"(a[0]), "r"(a[1]), "r"(a[2]), "r"(a[3]), "r"(b[0]), "r"(b[1]));
}
__device__ __forceinline__ void mma_f16(float* d, const uint32_t* a, const uint32_t* b) {
    asm volatile(
        "mma.sync.aligned.m16n8k16.row.col.f32.f16.f16.f32 "
        "{%0,%1,%2,%3}, {%4,%5,%6,%7}, {%8,%9}, {%0,%1,%2,%3};"
        : "+f"(d[0]), "+f"(d[1]), "+f"(d[2]), "+f"(d[3])
        : "r"(a[0]), "r"(a[1]), "r"(a[2]), "r"(a[3]), "r"(b[0]), "r"(b[1]));
}

#define SROWB  144          // padded row stride (64 elems * 2B = 128B + 16B pad)
#define MM_SMEM2 110592     // MF=2 3-pass: 2 stages * (2*64 + 2*128) rows * 144B
#define MM_SMEM1 73728      // MF=4 1-pass: 2 stages * (1*128 + 1*128) rows * 144B

// =========================================================================
// multi-pass mma GEMM. CTA tile (MF*32) x 128, K-step 64, 2 stages.
// NPASS=3: A hi/lo, B hi/lo (bf16). NPASS=1: A hi, B hi (fp16).
// epi: 0=store fp32, 1=add fp32, 2=gelu->hi/lo bf16, 3=wact, 4=silu
// =========================================================================
template<int MF, int NPASS, bool FP16>
__device__ __forceinline__ void mma_gemm_body(
    const void* __restrict__ Ahv, const void* __restrict__ Alv,
    const void* __restrict__ Bhv, const void* __restrict__ Blv,
    float* __restrict__ C, __nv_bfloat16* __restrict__ Ch, __nv_bfloat16* __restrict__ Cl,
    int N, int K, int epi, const float* __restrict__ aux)
{
    const __nv_bfloat16* Ah = (const __nv_bfloat16*)Ahv;
    const __nv_bfloat16* Al = (const __nv_bfloat16*)Alv;
    const __nv_bfloat16* Bh = (const __nv_bfloat16*)Bhv;
    const __nv_bfloat16* Bl = (const __nv_bfloat16*)Blv;

    extern __shared__ char sm[];
    uint32_t sb = s2u(sm);
    const int BM  = MF * 32;
    const int NA  = (NPASS >= 2) ? 2 : 1;
    const int NB  = (NPASS == 3) ? 2 : 1;
    const int AB  = BM * SROWB;
    const int BB  = 128 * SROWB;
    const int STG = NA * AB + NB * BB;
    const int AH_OFF = 0, AL_OFF = AB, BH_OFF = NA * AB, BL_OFF = NA * AB + BB;

    int tid = threadIdx.x, lane = tid & 31, wid = tid >> 5;
    int m0 = blockIdx.y * BM, n0 = blockIdx.x * 128;
    int m0w = (wid & 1) * (MF * 16), n0w = (wid >> 1) * 32;

    float acc[MF][4][4];
    #pragma unroll
    for (int a = 0; a < MF; a++)
        #pragma unroll
        for (int b = 0; b < 4; b++)
            #pragma unroll
            for (int c = 0; c < 4; c++) acc[a][b][c] = 0.0f;

    const int nt = K >> 6;
    int arow = tid >> 3, ac = (tid & 7) * 8;
    uint32_t aso = arow * SROWB + (tid & 7) * 16;

    // prologue: stage 0
    {
        uint32_t base = sb;
        #pragma unroll
        for (int i = 0; i < MF; i++) {
            int row = arow + i * 32;
            uint32_t so = aso + i * 32 * SROWB;
            size_t ga = (size_t)(m0 + row) * K + ac;
            cp16(base + AH_OFF + so, Ah + ga);
            if (NPASS >= 2) cp16(base + AL_OFF + so, Al + ga);
        }
        #pragma unroll
        for (int i = 0; i < 4; i++) {
            int row = arow + i * 32;
            uint32_t so = aso + i * 32 * SROWB;
            size_t gb = (size_t)(n0 + row) * K + ac;
            cp16(base + BH_OFF + so, Bh + gb);
            if (NPASS == 3) cp16(base + BL_OFF + so, Bl + gb);
        }
        asm volatile("cp.async.commit_group;" ::: "memory");
    }

    for (int t = 0; t < nt; t++) {
        if (t + 1 < nt) {
            int k0 = (t + 1) << 6;
            uint32_t base = sb + ((t + 1) & 1) * STG;
            #pragma unroll
            for (int i = 0; i < MF; i++) {
                int row = arow + i * 32;
                uint32_t so = aso + i * 32 * SROWB;
                size_t ga = (size_t)(m0 + row) * K + k0 + ac;
                cp16(base + AH_OFF + so, Ah + ga);
                if (NPASS >= 2) cp16(base + AL_OFF + so, Al + ga);
            }
            #pragma unroll
            for (int i = 0; i < 4; i++) {
                int row = arow + i * 32;
                uint32_t so = aso + i * 32 * SROWB;
                size_t gb = (size_t)(n0 + row) * K + k0 + ac;
                cp16(base + BH_OFF + so, Bh + gb);
                if (NPASS == 3) cp16(base + BL_OFF + so, Bl + gb);
            }
            asm volatile("cp.async.commit_group;" ::: "memory");
            asm volatile("cp.async.wait_group 1;" ::: "memory");
        } else {
            asm volatile("cp.async.wait_group 0;" ::: "memory");
        }
        __syncthreads();

        uint32_t base = sb + (t & 1) * STG;
        #pragma unroll
        for (int kk = 0; kk < 4; kk++) {
            uint32_t aoff = (uint32_t)((m0w + (lane & 15)) * SROWB
                           + kk * 32 + (lane >> 4) * 16);
            uint32_t boff = (uint32_t)((n0w + (lane & 7) + ((lane >> 4) << 3)) * SROWB
                           + kk * 32 + ((lane >> 3) & 1) * 16);
            uint32_t aH[MF][4], aL[MF][4], bH[2][4], bL[2][4];
            #pragma unroll
            for (int mf = 0; mf < MF; mf++)
                ldm_x4(aH[mf], base + AH_OFF + aoff + mf * 16 * SROWB);
            #pragma unroll
            for (int bb = 0; bb < 2; bb++)
                ldm_x4(bH[bb], base + BH_OFF + boff + bb * 16 * SROWB);
            #pragma unroll
            for (int mf = 0; mf < MF; mf++)
                #pragma unroll
                for (int nf = 0; nf < 4; nf++) {
                    if (FP16) mma_f16 (acc[mf][nf], aH[mf], &bH[nf >> 1][(nf & 1) * 2]);
                    else      mma_bf16(acc[mf][nf], aH[mf], &bH[nf >> 1][(nf & 1) * 2]);
                }
            if (NPASS >= 2) {
                #pragma unroll
                for (int mf = 0; mf < MF; mf++)
                    ldm_x4(aL[mf], base + AL_OFF + aoff + mf * 16 * SROWB);
                #pragma unroll
                for (int mf = 0; mf < MF; mf++)
                    #pragma unroll
                    for (int nf = 0; nf < 4; nf++) {
                        if (FP16) mma_f16 (acc[mf][nf], aL[mf], &bH[nf >> 1][(nf & 1) * 2]);
                        else      mma_bf16(acc[mf][nf], aL[mf], &bH[nf >> 1][(nf & 1) * 2]);
                    }
            }
            if (NPASS == 3) {
                #pragma unroll
                for (int bb = 0; bb < 2; bb++)
                    ldm_x4(bL[bb], base + BL_OFF + boff + bb * 16 * SROWB);
                #pragma unroll
                for (int mf = 0; mf < MF; mf++)
                    #pragma unroll
                    for (int nf = 0; nf < 4; nf++) {
                        if (FP16) mma_f16 (acc[mf][nf], aH[mf], &bL[nf >> 1][(nf & 1) * 2]);
                        else      mma_bf16(acc[mf][nf], aH[mf], &bL[nf >> 1][(nf & 1) * 2]);
                    }
            }
        }
        __syncthreads();
    }

    // ---- epilogue ----
    int qr = lane >> 2, qc = (lane & 3) * 2;
    #pragma unroll
    for (int mf = 0; mf < MF; mf++) {
        #pragma unroll
        for (int nf = 0; nf < 4; nf++) {
            #pragma unroll
            for (int half = 0; half < 2; half++) {
                int row = m0 + m0w + mf * 16 + qr + half * 8;
                int col = n0 + n0w + nf * 8 + qc;
                float x = acc[mf][nf][half * 2 + 0];
                float y = acc[mf][nf][half * 2 + 1];
                size_t o = (size_t)row * N + col;
                if (epi == 0) {
                    *(float2*)(C + o) = make_float2(x, y);
                } else if (epi == 1) {
                    float2 old = *(const float2*)(C + o);
                    *(float2*)(C + o) = make_float2(old.x + x, old.y + y);
                } else if (epi == 2) {
                    x = 0.5f * x * (1.0f + erff(x * 0.70710678118654752f));
                    y = 0.5f * y * (1.0f + erff(y * 0.70710678118654752f));
                    __nv_bfloat162 hv = __floats2bfloat162_rn(x, y);
                    float lx = x - __bfloat162float(__low2bfloat16(hv));
                    float ly = y - __bfloat162float(__high2bfloat16(hv));
                    *(__nv_bfloat162*)(Ch + o) = hv;
                    *(__nv_bfloat162*)(Cl + o) = __floats2bfloat162_rn(lx, ly);
                } else if (epi == 3) {
                    x = expf(-expf(x + aux[col]));
                    y = expf(-expf(y + aux[col + 1]));
                    *(float2*)(C + o) = make_float2(x, y);
                } else {
                    x = x / (1.0f + expf(-x));
                    y = y / (1.0f + expf(-y));
                    *(float2*)(C + o) = make_float2(x, y);
                }
            }
        }
    }
}

__global__ void __launch_bounds__(256, 2)
mma_gemm2(const __nv_bfloat16* __restrict__ Ah, const __nv_bfloat16* __restrict__ Al,
          const __nv_bfloat16* __restrict__ Bh, const __nv_bfloat16* __restrict__ Bl,
          float* __restrict__ C, __nv_bfloat16* __restrict__ Ch,
          __nv_bfloat16* __restrict__ Cl, int N, int K, int epi,
          const float* __restrict__ aux) {
    mma_gemm_body<2, 3, false>(Ah, Al, Bh, Bl, C, Ch, Cl, N, K, epi, aux);
}

// fp16 1-pass GEMM (logits): A fp16, B fp16
__global__ void __launch_bounds__(256, 2)
mma_gemm_h1(const __half* __restrict__ Ah, const __half* __restrict__ Bh,
            float* __restrict__ C, int N, int K) {
    mma_gemm_body<4, 1, true>(Ah, nullptr, Bh, nullptr, C, nullptr, nullptr, N, K, 0, nullptr);
}

// batched 5-projection: z selects A slice / weight / output / epilogue
__global__ void __launch_bounds__(256, 2)
proj_mma(const __nv_bfloat16* __restrict__ x5h, const __nv_bfloat16* __restrict__ x5l,
         const __nv_bfloat16* __restrict__ Ph, const __nv_bfloat16* __restrict__ Pl,
         int l, const float* __restrict__ w0,
         float* __restrict__ Cr, float* __restrict__ Ck, float* __restrict__ Cv,
         float* __restrict__ Cw, float* __restrict__ Cg) {
    int z = blockIdx.z;
    size_t wo = ((size_t)l * 5 + z) * DDm;
    float* C = (z == 0) ? Cr : (z == 1) ? Ck : (z == 2) ? Cv : (z == 3) ? Cw : Cg;
    int epi = (z == 3) ? 3 : (z == 4) ? 4 : 0;
    mma_gemm_body<2, 3, false>(x5h + (size_t)z * ND, x5l + (size_t)z * ND,
                               Ph + wo, Pl + wo, C, nullptr, nullptr, Dd, Dd, epi, w0);
}

// =========================================================================
// weight prep: transpose [K,N] -> [N,K] with bf16 hi/lo split
// =========================================================================
__global__ void tsplit(const float* __restrict__ W, __nv_bfloat16* __restrict__ oh,
                       __nv_bfloat16* __restrict__ ol, int K, int N) {
    __shared__ float ts[32][33];
    size_t mo = (size_t)blockIdx.z * K * N;
    int n0 = blockIdx.x * 32, k0 = blockIdx.y * 32;
    int tx = threadIdx.x, ty = threadIdx.y;
    #pragma unroll
    for (int r = 0; r < 4; r++)
        ts[ty + 8 * r][tx] = W[mo + (size_t)(k0 + ty + 8 * r) * N + n0 + tx];
    __syncthreads();
    #pragma unroll
    for (int r = 0; r < 4; r++) {
        float a = ts[tx][ty + 8 * r];
        float h = __bfloat162float(__float2bfloat16(a));
        size_t o = mo + (size_t)(n0 + ty + 8 * r) * K + k0 + tx;
        oh[o] = __float2bfloat16(a);
        ol[o] = __float2bfloat16(a - h);
    }
}

// proj (z<40: 5 weights x 8 layers) + Wo (z in [40,48))
__global__ void tsplit_projWo(const float* __restrict__ Wr, const float* __restrict__ Wk,
                              const float* __restrict__ Wv, const float* __restrict__ Ww,
                              const float* __restrict__ Wg, const float* __restrict__ Wo,
                              __nv_bfloat16* __restrict__ ph, __nv_bfloat16* __restrict__ pl,
                              __nv_bfloat16* __restrict__ ohd, __nv_bfloat16* __restrict__ old_) {
    __shared__ float ts[32][33];
    int z = blockIdx.z;
    const float* W;
    __nv_bfloat16 *oh, *ol;
    size_t mo;
    if (z < 40) {
        int p = z % 5, l = z / 5;
        W = ((p == 0) ? Wr : (p == 1) ? Wk : (p == 2) ? Wv :
             (p == 3) ? Ww : Wg) + (size_t)l * DDm;
        mo = (size_t)z * DDm;
        oh = ph; ol = pl;
    } else {
        int l = z - 40;
        W = Wo + (size_t)l * DDm;
        mo = (size_t)l * DDm;
        oh = ohd; ol = old_;
    }
    int n0 = blockIdx.x * 32, k0 = blockIdx.y * 32;
    int tx = threadIdx.x, ty = threadIdx.y;
    #pragma unroll
    for (int r = 0; r < 4; r++)
        ts[ty + 8 * r][tx] = W[(size_t)(k0 + ty + 8 * r) * Dd + n0 + tx];
    __syncthreads();
    #pragma unroll
    for (int r = 0; r < 4; r++) {
        float a = ts[tx][ty + 8 * r];
        float h = __bfloat162float(__float2bfloat16(a));
        size_t o = mo + (size_t)(n0 + ty + 8 * r) * Dd + k0 + tx;
        oh[o] = __float2bfloat16(a);
        ol[o] = __float2bfloat16(a - h);
    }
}

__global__ void esplit_f16(const float* __restrict__ e, __half* __restrict__ e16) {
    int idx = blockIdx.x * blockDim.x + threadIdx.x;
    e16[idx] = __float2half(e[idx]);
}

// =========================================================================
// embedding gather
// =========================================================================
__global__ void embed_kernel(const int* __restrict__ tok,
                             const float* __restrict__ emb,
                             float* __restrict__ h) {
    int idx = blockIdx.x * blockDim.x + threadIdx.x;
    int row = idx >> 7;
    int c4  = idx & 127;
    ((float4*)h)[idx] = ((const float4*)emb)[(size_t)tok[row] * 128 + c4];
}

// =========================================================================
// fused rmsnorm + token-shift + 5-way lerp -> hi/lo bf16. Block per row.
// =========================================================================
__global__ void __launch_bounds__(128)
rms_mix5(const float* __restrict__ h, const float* __restrict__ lnw,
         const float* __restrict__ mix,
         __nv_bfloat16* __restrict__ xh, __nv_bfloat16* __restrict__ xl) {
    int row = blockIdx.x, tid = threadIdx.x;
    int t = row & (Tt - 1);
    float4 a = ((const float4*)(h + (size_t)row * Dd))[tid];
    float4 p = (t == 0) ? make_float4(0, 0, 0, 0)
                        : ((const float4*)(h + (size_t)(row - 1) * Dd))[tid];
    float sc_ = a.x*a.x + a.y*a.y + a.z*a.z + a.w*a.w;
    float sp_ = p.x*p.x + p.y*p.y + p.z*p.z + p.w*p.w;
    #pragma unroll
    for (int s = 16; s > 0; s >>= 1) {
        sc_ += __shfl_xor_sync(0xffffffffu, sc_, s);
        sp_ += __shfl_xor_sync(0xffffffffu, sp_, s);
    }
    __shared__ float rc[4], rp[4];
    if ((tid & 31) == 0) { rc[tid >> 5] = sc_; rp[tid >> 5] = sp_; }
    __syncthreads();
    float totc = rc[0] + rc[1] + rc[2] + rc[3];
    float totp = rp[0] + rp[1] + rp[2] + rp[3];
    float scc = rsqrtf(totc * (1.0f / Dd) + 1e-6f);
    float scp = (t == 0) ? 0.0f : rsqrtf(totp * (1.0f / Dd) + 1e-6f);
    float4 wv = ((const float4*)lnw)[tid];
    float cn[4] = {a.x * scc * wv.x, a.y * scc * wv.y, a.z * scc * wv.z, a.w * scc * wv.w};
    float pn[4] = {p.x * scp * wv.x, p.y * scp * wv.y, p.z * scp * wv.z, p.w * scp * wv.w};
    int c0 = tid * 4;
    size_t ro = (size_t)row * Dd + c0;
    #pragma unroll
    for (int j = 0; j < 5; j++) {
        #pragma unroll
        for (int i = 0; i < 4; i++) {
            float v = fmaf(pn[i] - cn[i], mix[j * Dd + c0 + i], cn[i]);
            float hv = __bfloat162float(__float2bfloat16(v));
            xh[(size_t)j * ND + ro + i] = __float2bfloat16(v);
            xl[(size_t)j * ND + ro + i] = __float2bfloat16(v - hv);
        }
    }
}

// hi/lo-out rmsnorm -> bf16 (feeds FFN W1)
__global__ void rmsnorm_split_kernel(const float* __restrict__ x,
                                     const float* __restrict__ w,
                                     __nv_bfloat16* __restrict__ oh,
                                     __nv_bfloat16* __restrict__ ol) {
    int row = blockIdx.x;
    int tid = threadIdx.x;
    float4 a = ((const float4*)(x + (size_t)row * Dd))[tid];
    float ss = a.x*a.x + a.y*a.y + a.z*a.z + a.w*a.w;
    #pragma unroll
    for (int s = 16; s > 0; s >>= 1) ss += __shfl_xor_sync(0xffffffffu, ss, s);
    __shared__ float sred[4];
    if ((tid & 31) == 0) sred[tid >> 5] = ss;
    __syncthreads();
    float tot = sred[0] + sred[1] + sred[2] + sred[3];
    float sc  = rsqrtf(tot * (1.0f / Dd) + 1e-6f);
    float4 wv = ((const float4*)w)[tid];
    float vv[4] = {a.x * sc * wv.x, a.y * sc * wv.y, a.z * sc * wv.z, a.w * sc * wv.w};
    size_t o = (size_t)row * Dd + tid * 4;
    #pragma unroll
    for (int i = 0; i < 4; i++) {
        float h = __bfloat162float(__float2bfloat16(vv[i]));
        oh[o + i] = __float2bfloat16(vv[i]);
        ol[o + i] = __float2bfloat16(vv[i] - h);
    }
}

// fp16-out rmsnorm (feeds 1-pass logits GEMM)
__global__ void rmsnorm_f16(const float* __restrict__ x,
                            const float* __restrict__ w,
                            __half* __restrict__ oh) {
    int row = blockIdx.x;
    int tid = threadIdx.x;
    float4 a = ((const float4*)(x + (size_t)row * Dd))[tid];
    float ss = a.x*a.x + a.y*a.y + a.z*a.z + a.w*a.w;
    #pragma unroll
    for (int s = 16; s > 0; s >>= 1) ss += __shfl_xor_sync(0xffffffffu, ss, s);
    __shared__ float sred[4];
    if ((tid & 31) == 0) sred[tid >> 5] = ss;
    __syncthreads();
    float tot = sred[0] + sred[1] + sred[2] + sred[3];
    float sc  = rsqrtf(tot * (1.0f / Dd) + 1e-6f);
    float4 wv = ((const float4*)w)[tid];
    size_t o = (size_t)row * Dd + tid * 4;
    oh[o + 0] = __float2half(a.x * sc * wv.x);
    oh[o + 1] = __float2half(a.y * sc * wv.y);
    oh[o + 2] = __float2half(a.z * sc * wv.z);
    oh[o + 3] = __float2half(a.w * sc * wv.w);
}

// =========================================================================
// WKV phase 1: per-chunk local recurrence
// =========================================================================
__global__ void __launch_bounds__(128, 3)
wkv_chunk_kernel(float* __restrict__ r, const float* __restrict__ k,
                 const float* __restrict__ v, const float* __restrict__ w,
                 const float* __restrict__ u, float* __restrict__ y,
                 float* __restrict__ Sb, float* __restrict__ wt) {
    int blk = blockIdx.x;
    int bh  = blk / NCH;
    int ch  = blk % NCH;
    int b = bh >> 2, h = bh & 3;
    int j = threadIdx.x;
    __shared__ float4 s[Dh];
    float uj = u[h * Dh + j];
    float S[Dh];
    #pragma unroll
    for (int i = 0; i < Dh; i++) S[i] = 0.0f;
    float p = 1.0f;
    size_t off = (size_t)b * Tt * Dd + (size_t)(ch * CSZ) * Dd + h * Dh + j;
    for (int t = 0; t < CSZ; t++, off += Dd) {
        float rv = r[off], kv_ = k[off], wv = w[off], vv = v[off];
        __syncthreads();
        s[j] = make_float4(rv, kv_, wv, uj);
        __syncthreads();
        r[off] = rv * p;
        p *= wv;
        float acc = 0.0f;
        #pragma unroll
        for (int i = 0; i < Dh; i++) {
            float4 q = s[i];
            float kv = q.y * vv;
            acc  = fmaf(q.x, fmaf(q.w, kv, S[i]), acc);
            S[i] = fmaf(q.z, S[i], kv);
        }
        y[off] = acc;
    }
    wt[blk * Dh + j] = p;
    size_t base = (size_t)blk * Dh * Dh;
    #pragma unroll
    for (int i = 0; i < Dh; i++) Sb[base + (size_t)i * Dh + j] = S[i];
}

// =========================================================================
// WKV phase 2: parallel elementwise scan over chunks. One thread per (bh,i,j).
// =========================================================================
__global__ void __launch_bounds__(256)
wkv_combine_kernel(float* __restrict__ Sb, const float* __restrict__ wt) {
    int idx = blockIdx.x * blockDim.x + threadIdx.x;   // over Bb*Hh*Dh*Dh
    int bh  = idx >> 14;
    int rem = idx & 16383;
    int i   = rem >> 7;
    float run = 0.0f;
    #pragma unroll 4
    for (int ch = 0; ch < NCH; ch++) {
        int blk = bh * NCH + ch;
        size_t o = ((size_t)blk << 14) + rem;
        float m = Sb[o];
        Sb[o] = run;
        run = fmaf(run, wt[blk * Dh + i], m);
    }
}

// =========================================================================
// WKV phase 3 + GroupNorm + gate fused. Block per (bh,chunk), 128 threads.
// =========================================================================
__global__ void __launch_bounds__(128, 3)
wkv_inter_gn_kernel(const float* __restrict__ rt, const float* __restrict__ Sb,
                    const float* __restrict__ y, const float* __restrict__ g,
                    const float* __restrict__ gw, const float* __restrict__ gb,
                    __nv_bfloat16* __restrict__ oh, __nv_bfloat16* __restrict__ ol) {
    int blk = blockIdx.x;
    int bh  = blk / NCH;
    int ch  = blk % NCH;
    int b = bh >> 2, h = bh & 3;
    int j = threadIdx.x;
    int lane = j & 31, wid = j >> 5;
    float Scol[Dh];
    size_t base = (size_t)blk * Dh * Dh;
    #pragma unroll
    for (int i = 0; i < Dh; i++) Scol[i] = Sb[base + (size_t)i * Dh + j];
    __shared__ float sr[Dh];
    __shared__ float r1[4], r2[4];
    int c = h * Dh + j;
    float gwj = gw[c], gbj = gb[c];
    size_t off = (size_t)b * Tt * Dd + (size_t)(ch * CSZ) * Dd + h * Dh + j;
    for (int t = 0; t < CSZ; t++, off += Dd) {
        __syncthreads();
        sr[j] = rt[off];
        __syncthreads();
        float acc = y[off];
        #pragma unroll
        for (int i = 0; i < Dh; i++) acc = fmaf(sr[i], Scol[i], acc);
        float s1 = acc, s2 = acc * acc;
        #pragma unroll
        for (int s = 16; s > 0; s >>= 1) {
            s1 += __shfl_xor_sync(0xffffffffu, s1, s);
            s2 += __shfl_xor_sync(0xffffffffu, s2, s);
        }
        if (lane == 0) { r1[wid] = s1; r2[wid] = s2; }
        __syncthreads();
        s1 = r1[0] + r1[1] + r1[2] + r1[3];
        s2 = r2[0] + r2[1] + r2[2] + r2[3];
        float mu  = s1 * (1.0f / Dh);
        float var = s2 * (1.0f / Dh) - mu * mu;
        float nrm = (acc - mu) * rsqrtf(var + 1e-5f);
        float val = fmaf(nrm, gwj, gbj) * g[off];
        float hv = __bfloat162float(__float2bfloat16(val));
        oh[off] = __float2bfloat16(val);
        ol[off] = __float2bfloat16(val - hv);
    }
}

// =========================================================================
// host driver
// =========================================================================
extern "C" void kernel_launch(void* const* d_in, const int* in_sizes, int n_in,
                              void* d_out, int out_size) {
    const int*   tokens = (const int*)  d_in[0];
    const float* embed  = (const float*)d_in[1];
    const float* ln1    = (const float*)d_in[2];
    const float* ln2    = (const float*)d_in[3];
    const float* lno    = (const float*)d_in[4];
    const float* mix    = (const float*)d_in[5];
    const float* Wr     = (const float*)d_in[6];
    const float* Wk     = (const float*)d_in[7];
    const float* Wv     = (const float*)d_in[8];
    const float* Wg     = (const float*)d_in[9];
    const float* Ww     = (const float*)d_in[10];
    const float* w0     = (const float*)d_in[11];
    const float* Wo     = (const float*)d_in[12];
    const float* u      = (const float*)d_in[13];
    const float* gnw    = (const float*)d_in[14];
    const float* gnb    = (const float*)d_in[15];
    const float* W1     = (const float*)d_in[16];
    const float* W2     = (const float*)d_in[17];
    float* out = (float*)d_out;

    float *h, *r, *k, *v, *w, *g, *y, *Sb, *wt;
    cudaGetSymbolAddress((void**)&h,  g_h);
    cudaGetSymbolAddress((void**)&r,  g_r);
    cudaGetSymbolAddress((void**)&k,  g_k);
    cudaGetSymbolAddress((void**)&v,  g_v);
    cudaGetSymbolAddress((void**)&w,  g_w);
    cudaGetSymbolAddress((void**)&g,  g_g);
    cudaGetSymbolAddress((void**)&y,  g_y);
    cudaGetSymbolAddress((void**)&Sb, g_Sb);
    cudaGetSymbolAddress((void**)&wt, g_wt);

    __nv_bfloat16 *x5h, *x5l, *ffh, *ffl, *hnh, *hnl, *gnh, *gnl;
    __nv_bfloat16 *pTh, *pTl, *oTh, *oTl, *t1h, *t1l, *t2h, *t2l;
    __half *e16, *h16;
    cudaGetSymbolAddress((void**)&x5h, g_x5h);
    cudaGetSymbolAddress((void**)&x5l, g_x5l);
    cudaGetSymbolAddress((void**)&ffh, g_ffh);
    cudaGetSymbolAddress((void**)&ffl, g_ffl);
    cudaGetSymbolAddress((void**)&hnh, g_hnh);
    cudaGetSymbolAddress((void**)&hnl, g_hnl);
    cudaGetSymbolAddress((void**)&gnh, g_gnh);
    cudaGetSymbolAddress((void**)&gnl, g_gnl);
    cudaGetSymbolAddress((void**)&pTh, g_pTh);
    cudaGetSymbolAddress((void**)&pTl, g_pTl);
    cudaGetSymbolAddress((void**)&oTh, g_oTh);
    cudaGetSymbolAddress((void**)&oTl, g_oTl);
    cudaGetSymbolAddress((void**)&t1h, g_1Th);
    cudaGetSymbolAddress((void**)&t1l, g_1Tl);
    cudaGetSymbolAddress((void**)&t2h, g_2Th);
    cudaGetSymbolAddress((void**)&t2l, g_2Tl);
    cudaGetSymbolAddress((void**)&e16, g_e16);
    cudaGetSymbolAddress((void**)&h16, g_h16);

    cudaFuncSetAttribute(mma_gemm2,   cudaFuncAttributeMaxDynamicSharedMemorySize, MM_SMEM2);
    cudaFuncSetAttribute(mma_gemm_h1, cudaFuncAttributeMaxDynamicSharedMemorySize, MM_SMEM1);
    cudaFuncSetAttribute(proj_mma,    cudaFuncAttributeMaxDynamicSharedMemorySize, MM_SMEM2);

    dim3 tb(32, 8);
    dim3 gridProj(4, 32, 5);          // 64x128 tiles, 5 projections
    dim3 grid512n(4, 32);             // 64x128 tiles for N=512 GEMMs
    dim3 gridF   (16, 32);            // W1 (N=2048), 64x128 tiles
    dim3 gridV   (250, 16);           // logits, 128x128 tiles (fp16 1-pass)

    // launch order: harness prepends 2 launches; ncu -s 5 -c 1 captures
    // global #6 = our #4 = proj_mma(l=0).
    tsplit_projWo<<<dim3(16, 16, 48), tb>>>(Wr, Wk, Wv, Ww, Wg, Wo, pTh, pTl, oTh, oTl);
    embed_kernel<<<(ND / 4) / 256, 256>>>(tokens, embed, h);
    rms_mix5<<<Nrows, 128>>>(h, ln1, mix, x5h, x5l);
    proj_mma<<<gridProj, 256, MM_SMEM2>>>(x5h, x5l, pTh, pTl, 0, w0, r, k, v, w, g);

    tsplit<<<dim3(Ff / 32, 16, Ll), tb>>>(W1, t1h, t1l, Dd, Ff);
    tsplit<<<dim3(16, Ff / 32, Ll), tb>>>(W2, t2h, t2l, Ff, Dd);
    esplit_f16<<<(Vv * Dd) / 256, 256>>>(embed, e16);

    for (int l = 0; l < Ll; l++) {
        if (l > 0) {
            rms_mix5<<<Nrows, 128>>>(h, ln1 + l * Dd, mix + (size_t)l * 5 * Dd, x5h, x5l);
            proj_mma<<<gridProj, 256, MM_SMEM2>>>(x5h, x5l, pTh, pTl, l, w0 + l * Dd,
                                                  r, k, v, w, g);
        }

        wkv_chunk_kernel  <<<Bb * Hh * NCH, 128>>>(r, k, v, w, u + l * Hh * Dh, y, Sb, wt);
        wkv_combine_kernel<<<(Bb * Hh * Dh * Dh) / 256, 256>>>(Sb, wt);
        wkv_inter_gn_kernel<<<Bb * Hh * NCH, 128>>>(r, Sb, y, g,
                                                    gnw + l * Dd, gnb + l * Dd, gnh, gnl);

        mma_gemm2<<<grid512n, 256, MM_SMEM2>>>(gnh, gnl, oTh + (size_t)l * DDm,
                                               oTl + (size_t)l * DDm, h, nullptr, nullptr,
                                               Dd, Dd, 1, nullptr);

        rmsnorm_split_kernel<<<Nrows, 128>>>(h, ln2 + l * Dd, hnh, hnl);
        mma_gemm2<<<gridF, 256, MM_SMEM2>>>(hnh, hnl, t1h + (size_t)l * Dd * Ff,
                                            t1l + (size_t)l * Dd * Ff, nullptr, ffh, ffl,
                                            Ff, Dd, 2, nullptr);
        mma_gemm2<<<grid512n, 256, MM_SMEM2>>>(ffh, ffl, t2h + (size_t)l * Ff * Dd,
                                               t2l + (size_t)l * Ff * Dd, h, nullptr, nullptr,
                                               Dd, Ff, 1, nullptr);
    }

    rmsnorm_f16<<<Nrows, 128>>>(h, lno, h16);
    mma_gemm_h1<<<gridV, 256, MM_SMEM1>>>(h16, e16, out, Vv, Dd);
}